// round 17
// baseline (speedup 1.0000x reference)
#include <cuda_runtime.h>
#include <math.h>

// Problem dims
#define B 8
#define S 4096
#define F 128
#define T 16
#define THRESH 0.1f
#define EPS 1e-8f

// Stats tiling (measured-stable shape)
#define NCHUNK 64
#define TY 8
#define RUN 8
#define STATS_BLOCKS (NCHUNK * B)        // 512
#define MAIN_BLOCKS (B * S * (F / 4) / 256)        // 4096

// Scratch: per-(b,f) double accumulators (16KB — tiny last-block reduce).
__device__ double g_sum[B * F];
__device__ double g_sumsq[B * F];
__device__ __align__(16) float g_inv[B * F];
__device__ unsigned g_count;

// Stats + fused last-block g_inv. 512 blocks, ~10-11us.
__global__ void k_pre(const float4* __restrict__ x) {
    int f4 = threadIdx.x;     // 0..31
    int ty = threadIdx.y;     // 0..7
    int tid = ty * 32 + f4;   // 0..255
    int chunk = blockIdx.x & (NCHUNK - 1);
    int b = blockIdx.x >> 6;

    int s_start = chunk * (TY * RUN) + ty * RUN;
    const float4* p = x + (size_t)b * S * 32 + (size_t)s_start * 32 + f4;

    float4 prev = (s_start == 0) ? p[0] : p[-32];   // prepend: diff[0] = 0

    float4 s1 = make_float4(0.f, 0.f, 0.f, 0.f);
    float4 s2 = make_float4(0.f, 0.f, 0.f, 0.f);
    #pragma unroll
    for (int j = 0; j < RUN; j++) {
        float4 cur = *p;
        p += 32;
        float dx = cur.x - prev.x, dy = cur.y - prev.y;
        float dz = cur.z - prev.z, dw = cur.w - prev.w;
        s1.x += dx; s1.y += dy; s1.z += dz; s1.w += dw;
        s2.x += dx * dx; s2.y += dy * dy; s2.z += dz * dz; s2.w += dw * dw;
        prev = cur;
    }

    __shared__ float4 sh1[TY][32];
    __shared__ float4 sh2[TY][32];
    sh1[ty][f4] = s1;
    sh2[ty][f4] = s2;
    __syncthreads();

    if (ty == 0) {
        float4 t1 = make_float4(0.f, 0.f, 0.f, 0.f);
        #pragma unroll
        for (int j = 0; j < TY; j++) {
            float4 a = sh1[j][f4];
            t1.x += a.x; t1.y += a.y; t1.z += a.z; t1.w += a.w;
        }
        int idx = b * F + f4 * 4;
        atomicAdd(&g_sum[idx + 0], (double)t1.x);
        atomicAdd(&g_sum[idx + 1], (double)t1.y);
        atomicAdd(&g_sum[idx + 2], (double)t1.z);
        atomicAdd(&g_sum[idx + 3], (double)t1.w);
        __threadfence();   // producer fence before ticket
    } else if (ty == 1) {
        float4 t2 = make_float4(0.f, 0.f, 0.f, 0.f);
        #pragma unroll
        for (int j = 0; j < TY; j++) {
            float4 c = sh2[j][f4];
            t2.x += c.x; t2.y += c.y; t2.z += c.z; t2.w += c.w;
        }
        int idx = b * F + f4 * 4;
        atomicAdd(&g_sumsq[idx + 0], (double)t2.x);
        atomicAdd(&g_sumsq[idx + 1], (double)t2.y);
        atomicAdd(&g_sumsq[idx + 2], (double)t2.z);
        atomicAdd(&g_sumsq[idx + 3], (double)t2.w);
        __threadfence();
    }

    __shared__ bool amLast;
    __syncthreads();
    if (tid == 0)
        amLast = (atomicAdd(&g_count, 1u) == STATS_BLOCKS - 1);
    __syncthreads();
    if (amLast) {
        #pragma unroll
        for (int k = tid; k < B * F; k += 256) {
            double sum = __ldcg(&g_sum[k]);
            double sumsq = __ldcg(&g_sumsq[k]);
            double m = sum / (double)S;
            double var = sumsq / (double)S - m * m;
            if (var < 0.0) var = 0.0;
            float sd = (float)sqrt(var);
            g_inv[k] = 1.0f / (sd + EPS);
            g_sum[k] = 0.0;     // re-zero for next call / graph replay
            g_sumsq[k] = 0.0;
        }
        __syncthreads();
        if (tid == 0) g_count = 0;
    }
}

// Full expansion with PDL: pre-sync phase writes this thread's 5 zero slices
// (stcs: write-once data, keep input L2-resident) WHILE k_pre is still
// running; after the grid-dependency sync, read input and write 11 pos/neg.
__global__ void k_main(const float4* __restrict__ x, float4* __restrict__ out) {
    int i = blockIdx.x * 256 + threadIdx.x;  // 0 .. B*S*(F/4)-1
    int f4 = i & 31;
    int s  = (i >> 5) & 4095;
    int b  = i >> 17;

    const size_t tstride = (size_t)S * 32;
    size_t obase = ((size_t)b * T * S + s) * 32 + f4;

    // ---- pre-sync: zero slices t = 2,5,8,11,14 (no dependency on k_pre) ----
    const float4 zero = make_float4(0.f, 0.f, 0.f, 0.f);
    #pragma unroll
    for (int t = 2; t < T; t += 3)
        __stcs(&out[obase + (size_t)t * tstride], zero);

    cudaGridDependencySynchronize();

    // ---- post-sync: stats-dependent pos/neg slices ----
    float4 cur = x[i];
    float4 prv = (s == 0) ? cur : x[i - 32];

    const float4 inv4 = *reinterpret_cast<const float4*>(&g_inv[b * F + f4 * 4]);

    float ndx = (cur.x - prv.x) * inv4.x;
    float ndy = (cur.y - prv.y) * inv4.y;
    float ndz = (cur.z - prv.z) * inv4.z;
    float ndw = (cur.w - prv.w) * inv4.w;

    float4 pos, neg;
    pos.x = (ndx >=  THRESH) ? 1.f : 0.f;
    pos.y = (ndy >=  THRESH) ? 1.f : 0.f;
    pos.z = (ndz >=  THRESH) ? 1.f : 0.f;
    pos.w = (ndw >=  THRESH) ? 1.f : 0.f;
    neg.x = (-ndx >= THRESH) ? 1.f : 0.f;
    neg.y = (-ndy >= THRESH) ? 1.f : 0.f;
    neg.z = (-ndz >= THRESH) ? 1.f : 0.f;
    neg.w = (-ndw >= THRESH) ? 1.f : 0.f;

    #pragma unroll
    for (int t = 0; t < T; t++) {
        int ph = t % 3;
        if (ph == 2) continue;                      // zeros written pre-sync
        out[obase + (size_t)t * tstride] = (ph == 0) ? pos : neg;
    }
}

extern "C" void kernel_launch(void* const* d_in, const int* in_sizes, int n_in,
                              void* d_out, int out_size) {
    const float4* x = (const float4*)d_in[0];
    float4* out = (float4*)d_out;

    dim3 bt(32, TY);
    k_pre<<<STATS_BLOCKS, bt>>>(x);

    cudaLaunchAttribute attr[1];
    attr[0].id = cudaLaunchAttributeProgrammaticStreamSerialization;
    attr[0].val.programmaticStreamSerializationAllowed = 1;

    cudaLaunchConfig_t cfg = {};
    cfg.gridDim = dim3(MAIN_BLOCKS);
    cfg.blockDim = dim3(256);
    cfg.dynamicSmemBytes = 0;
    cfg.stream = 0;
    cfg.attrs = attr;
    cfg.numAttrs = 1;
    cudaLaunchKernelEx(&cfg, k_main, x, out);
}